// round 1
// baseline (speedup 1.0000x reference)
#include <cuda_runtime.h>
#include <cuda_bf16.h>
#include <math.h>

// ---------------- problem constants ----------------
#define BATCH 16
#define IMG 512
#define PATCH 16
#define CIN 3
#define DMODEL 384
#define NHEADS 4
#define HDIM 96
#define NBLOCKS 3
#define NCLS 2
#define NPATCH 1024          // (512/16)^2
#define SEQ 1025             // NPATCH + 1
#define FFDIM 1536
#define MROWS (BATCH * SEQ)  // 16400

// ---------------- scratch (static device, allowed) ----------------
__device__ float g_h   [(size_t)MROWS * DMODEL];
__device__ float g_hn  [(size_t)MROWS * DMODEL];
__device__ float g_q   [(size_t)MROWS * DMODEL];
__device__ float g_k   [(size_t)MROWS * DMODEL];
__device__ float g_v   [(size_t)MROWS * DMODEL];
__device__ float g_vals[(size_t)MROWS * DMODEL];
__device__ float g_f   [(size_t)MROWS * FFDIM];
__device__ float g_s   [(size_t)BATCH * NHEADS * SEQ * SEQ];  // 269 MB

// ---------------- generic SGEMM: C(MxN) = A(MxK) @ B(KxN) + epilogue ----------------
// BM=128 BN=128 BK=16, 256 threads, 8x8 micro-tile.
// EPI: 0=none, 1=bias, 2=bias+relu, 3=bias+residual(in C)
#define GBM 128
#define GBN 128
#define GBK 16

template <int EPI>
__global__ __launch_bounds__(256, 2)
void sgemm_kernel(const float* __restrict__ A, const float* __restrict__ B,
                  float* __restrict__ C, const float* __restrict__ bias,
                  int M, int N, int K)
{
    __shared__ float As[GBK][GBM + 4];
    __shared__ float Bs[GBK][GBN + 4];

    int tid = threadIdx.x;
    int tx = tid & 15;        // 0..15 -> N
    int ty = tid >> 4;        // 0..15 -> M
    int m0 = blockIdx.y * GBM;
    int n0 = blockIdx.x * GBN;

    int a_mi = tid >> 1;            // 0..127
    int a_k8 = (tid & 1) * 8;       // 0 or 8
    int b_ki = tid >> 4;            // 0..15
    int b_n8 = (tid & 15) * 8;      // 0..120

    float acc[8][8];
#pragma unroll
    for (int i = 0; i < 8; ++i)
#pragma unroll
        for (int j = 0; j < 8; ++j) acc[i][j] = 0.f;

    for (int k0 = 0; k0 < K; k0 += GBK) {
        // A tile: 128 x 16, coalesced along K
        int gm = m0 + a_mi;
        float4 av0, av1;
        if (gm < M) {
            const float* ap = A + (size_t)gm * K + k0 + a_k8;
            av0 = *(const float4*)ap;
            av1 = *(const float4*)(ap + 4);
        } else {
            av0 = make_float4(0.f, 0.f, 0.f, 0.f);
            av1 = av0;
        }
        As[a_k8 + 0][a_mi] = av0.x; As[a_k8 + 1][a_mi] = av0.y;
        As[a_k8 + 2][a_mi] = av0.z; As[a_k8 + 3][a_mi] = av0.w;
        As[a_k8 + 4][a_mi] = av1.x; As[a_k8 + 5][a_mi] = av1.y;
        As[a_k8 + 6][a_mi] = av1.z; As[a_k8 + 7][a_mi] = av1.w;

        // B tile: 16 x 128, coalesced along N
        const float* bp = B + (size_t)(k0 + b_ki) * N + n0 + b_n8;
        float4 bv0 = *(const float4*)bp;
        float4 bv1 = *(const float4*)(bp + 4);
        *(float4*)&Bs[b_ki][b_n8]     = bv0;
        *(float4*)&Bs[b_ki][b_n8 + 4] = bv1;

        __syncthreads();

#pragma unroll
        for (int kk = 0; kk < GBK; ++kk) {
            float4 a0 = *(const float4*)&As[kk][ty * 8];
            float4 a1 = *(const float4*)&As[kk][ty * 8 + 4];
            float4 b0 = *(const float4*)&Bs[kk][tx * 8];
            float4 b1 = *(const float4*)&Bs[kk][tx * 8 + 4];
            float a[8] = {a0.x, a0.y, a0.z, a0.w, a1.x, a1.y, a1.z, a1.w};
            float b[8] = {b0.x, b0.y, b0.z, b0.w, b1.x, b1.y, b1.z, b1.w};
#pragma unroll
            for (int i = 0; i < 8; ++i)
#pragma unroll
                for (int j = 0; j < 8; ++j)
                    acc[i][j] = fmaf(a[i], b[j], acc[i][j]);
        }
        __syncthreads();
    }

#pragma unroll
    for (int i = 0; i < 8; ++i) {
        int m = m0 + ty * 8 + i;
        if (m >= M) continue;
#pragma unroll
        for (int j = 0; j < 8; ++j) {
            int n = n0 + tx * 8 + j;
            size_t idx = (size_t)m * N + n;
            float r = acc[i][j];
            if (EPI == 1) r += bias[n];
            else if (EPI == 2) { r += bias[n]; r = fmaxf(r, 0.f); }
            else if (EPI == 3) { r += bias[n] + C[idx]; }
            C[idx] = r;
        }
    }
}

// ---------------- patch embedding: implicit-im2col GEMM ----------------
// M = 16384 patches, K = 768 (c,p,q), N = 384
__global__ __launch_bounds__(256, 2)
void patch_embed_kernel(const float* __restrict__ x, const float* __restrict__ cw,
                        const float* __restrict__ cb, const float* __restrict__ pos,
                        float* __restrict__ h)
{
    const int K = CIN * PATCH * PATCH;   // 768
    __shared__ float As[GBK][GBM + 4];
    __shared__ float Bs[GBK][GBM + 4];

    int tid = threadIdx.x;
    int tx = tid & 15, ty = tid >> 4;
    int m0 = blockIdx.y * GBM;
    int n0 = blockIdx.x * GBM;  // BN = 128 as well

    int a_mi = tid >> 1;
    int a_k8 = (tid & 1) * 8;
    int b_ni = tid >> 1;
    int b_k8 = (tid & 1) * 8;

    float acc[8][8];
#pragma unroll
    for (int i = 0; i < 8; ++i)
#pragma unroll
        for (int j = 0; j < 8; ++j) acc[i][j] = 0.f;

    for (int k0 = 0; k0 < K; k0 += GBK) {
        // A gather: patch gm, k = (c, p-row r, q)
        int gm = m0 + a_mi;
        int b  = gm >> 10;
        int pix = gm & 1023;
        int hp = pix >> 5, wp = pix & 31;
        int k  = k0 + a_k8;
        int c  = k >> 8, r = (k >> 4) & 15, q = k & 15;
        const float* xa = x + (((size_t)(b * CIN + c) * IMG + hp * PATCH + r) * IMG
                               + wp * PATCH + q);
        float4 av0 = *(const float4*)xa;
        float4 av1 = *(const float4*)(xa + 4);
        As[a_k8 + 0][a_mi] = av0.x; As[a_k8 + 1][a_mi] = av0.y;
        As[a_k8 + 2][a_mi] = av0.z; As[a_k8 + 3][a_mi] = av0.w;
        As[a_k8 + 4][a_mi] = av1.x; As[a_k8 + 5][a_mi] = av1.y;
        As[a_k8 + 6][a_mi] = av1.z; As[a_k8 + 7][a_mi] = av1.w;

        // B: conv_w is (N=384, K=768) row-major -> transpose load (coalesced along k)
        int gn = n0 + b_ni;
        const float* wa = cw + (size_t)gn * K + k0 + b_k8;
        float4 bv0 = *(const float4*)wa;
        float4 bv1 = *(const float4*)(wa + 4);
        Bs[b_k8 + 0][b_ni] = bv0.x; Bs[b_k8 + 1][b_ni] = bv0.y;
        Bs[b_k8 + 2][b_ni] = bv0.z; Bs[b_k8 + 3][b_ni] = bv0.w;
        Bs[b_k8 + 4][b_ni] = bv1.x; Bs[b_k8 + 5][b_ni] = bv1.y;
        Bs[b_k8 + 6][b_ni] = bv1.z; Bs[b_k8 + 7][b_ni] = bv1.w;

        __syncthreads();
#pragma unroll
        for (int kk = 0; kk < GBK; ++kk) {
            float4 a0 = *(const float4*)&As[kk][ty * 8];
            float4 a1 = *(const float4*)&As[kk][ty * 8 + 4];
            float4 b0 = *(const float4*)&Bs[kk][tx * 8];
            float4 b1 = *(const float4*)&Bs[kk][tx * 8 + 4];
            float a[8] = {a0.x, a0.y, a0.z, a0.w, a1.x, a1.y, a1.z, a1.w};
            float b[8] = {b0.x, b0.y, b0.z, b0.w, b1.x, b1.y, b1.z, b1.w};
#pragma unroll
            for (int i = 0; i < 8; ++i)
#pragma unroll
                for (int j = 0; j < 8; ++j)
                    acc[i][j] = fmaf(a[i], b[j], acc[i][j]);
        }
        __syncthreads();
    }

#pragma unroll
    for (int i = 0; i < 8; ++i) {
        int m = m0 + ty * 8 + i;
        int b = m >> 10, np = m & 1023;
#pragma unroll
        for (int j = 0; j < 8; ++j) {
            int n = n0 + tx * 8 + j;
            h[((size_t)b * SEQ + 1 + np) * DMODEL + n] =
                acc[i][j] + cb[n] + pos[(size_t)(1 + np) * DMODEL + n];
        }
    }
}

// ---------------- cls row ----------------
__global__ void cls_kernel(const float* __restrict__ cls_token,
                           const float* __restrict__ pos, float* __restrict__ h)
{
    int b = blockIdx.x, d = threadIdx.x;
    h[(size_t)b * SEQ * DMODEL + d] = cls_token[d] + pos[d];
}

// ---------------- LayerNorm over D=384, one row per block (128 thr) ----------------
__global__ void ln_kernel(const float* __restrict__ x, float* __restrict__ y,
                          const float* __restrict__ s, const float* __restrict__ bb)
{
    int row = blockIdx.x;
    const float* xr = x + (size_t)row * DMODEL;
    float* yr = y + (size_t)row * DMODEL;
    int tid = threadIdx.x;  // 128

    float v0 = xr[tid], v1 = xr[tid + 128], v2 = xr[tid + 256];

    __shared__ float red[128];
    red[tid] = v0 + v1 + v2;
    __syncthreads();
#pragma unroll
    for (int o = 64; o > 0; o >>= 1) {
        if (tid < o) red[tid] += red[tid + o];
        __syncthreads();
    }
    float mean = red[0] * (1.f / DMODEL);
    __syncthreads();

    float d0 = v0 - mean, d1 = v1 - mean, d2 = v2 - mean;
    red[tid] = d0 * d0 + d1 * d1 + d2 * d2;
    __syncthreads();
#pragma unroll
    for (int o = 64; o > 0; o >>= 1) {
        if (tid < o) red[tid] += red[tid + o];
        __syncthreads();
    }
    float var = red[0] * (1.f / DMODEL);
    float inv = rsqrtf(var + 1e-5f);

    yr[tid]       = d0 * inv * s[tid]       + bb[tid];
    yr[tid + 128] = d1 * inv * s[tid + 128] + bb[tid + 128];
    yr[tid + 256] = d2 * inv * s[tid + 256] + bb[tid + 256];
}

// ---------------- distance attention scores ----------------
// S[bh, q, k] = sqrt(sum_d (Q[q,d]-K[k,d])^2) * scale   (exactly |q-k|_2 * scale)
__global__ __launch_bounds__(256)
void scores_kernel(const float* __restrict__ Q, const float* __restrict__ K,
                   float* __restrict__ S)
{
    const float SCALE = 0.10206207261596577f;  // 1/sqrt(96)
    int bh = blockIdx.z;
    int b = bh >> 2, h = bh & 3;
    int q0 = blockIdx.y * 64;
    int k0 = blockIdx.x * 64;

    __shared__ float Qs[64][100];
    __shared__ float KsT[HDIM][68];

    int tid = threadIdx.x;
    int tx = tid & 15, ty = tid >> 4;

    // load 64 rows x 96 dims of Q and K (K transposed in smem)
#pragma unroll
    for (int i = 0; i < 6; ++i) {
        int e = tid + i * 256;           // 0..1535 float4 slots
        int row = e / 24, c4 = e % 24;
        int gq = q0 + row;
        float4 qv = (gq < SEQ)
            ? *(const float4*)(Q + ((size_t)b * SEQ + gq) * DMODEL + h * HDIM + c4 * 4)
            : make_float4(0.f, 0.f, 0.f, 0.f);
        *(float4*)&Qs[row][c4 * 4] = qv;

        int gk = k0 + row;
        float4 kv = (gk < SEQ)
            ? *(const float4*)(K + ((size_t)b * SEQ + gk) * DMODEL + h * HDIM + c4 * 4)
            : make_float4(0.f, 0.f, 0.f, 0.f);
        KsT[c4 * 4 + 0][row] = kv.x;
        KsT[c4 * 4 + 1][row] = kv.y;
        KsT[c4 * 4 + 2][row] = kv.z;
        KsT[c4 * 4 + 3][row] = kv.w;
    }
    __syncthreads();

    float acc[4][4];
#pragma unroll
    for (int i = 0; i < 4; ++i)
#pragma unroll
        for (int j = 0; j < 4; ++j) acc[i][j] = 0.f;

#pragma unroll 8
    for (int dd = 0; dd < HDIM; ++dd) {
        float4 kv = *(const float4*)&KsT[dd][tx * 4];
        float bj[4] = {kv.x, kv.y, kv.z, kv.w};
#pragma unroll
        for (int i = 0; i < 4; ++i) {
            float a = Qs[ty * 4 + i][dd];
#pragma unroll
            for (int j = 0; j < 4; ++j) {
                float d = a - bj[j];
                acc[i][j] = fmaf(d, d, acc[i][j]);
            }
        }
    }

#pragma unroll
    for (int i = 0; i < 4; ++i) {
        int q = q0 + ty * 4 + i;
        if (q >= SEQ) continue;
#pragma unroll
        for (int j = 0; j < 4; ++j) {
            int kI = k0 + tx * 4 + j;
            if (kI >= SEQ) continue;
            S[(size_t)bh * SEQ * SEQ + (size_t)q * SEQ + kI] =
                sqrtf(fmaxf(acc[i][j], 0.f)) * SCALE;
        }
    }
}

// ---------------- row softmax over SEQ=1025 ----------------
__global__ void softmax_kernel(float* __restrict__ S)
{
    float* r = S + (size_t)blockIdx.x * SEQ;
    int tid = threadIdx.x;  // 256
    float v[5];
    float mx = -1e30f;
#pragma unroll
    for (int i = 0; i < 5; ++i) {
        int idx = tid + i * 256;
        if (idx < SEQ) { v[i] = r[idx]; mx = fmaxf(mx, v[i]); }
        else v[i] = -1e30f;
    }
    __shared__ float red[256];
    red[tid] = mx;
    __syncthreads();
#pragma unroll
    for (int o = 128; o > 0; o >>= 1) {
        if (tid < o) red[tid] = fmaxf(red[tid], red[tid + o]);
        __syncthreads();
    }
    mx = red[0];
    __syncthreads();

    float sum = 0.f;
#pragma unroll
    for (int i = 0; i < 5; ++i) {
        int idx = tid + i * 256;
        if (idx < SEQ) { v[i] = __expf(v[i] - mx); sum += v[i]; }
    }
    red[tid] = sum;
    __syncthreads();
#pragma unroll
    for (int o = 128; o > 0; o >>= 1) {
        if (tid < o) red[tid] += red[tid + o];
        __syncthreads();
    }
    float inv = 1.f / red[0];
#pragma unroll
    for (int i = 0; i < 5; ++i) {
        int idx = tid + i * 256;
        if (idx < SEQ) r[idx] = v[i] * inv;
    }
}

// ---------------- vals = softmax(S) @ V (per batch-head) ----------------
__global__ __launch_bounds__(256)
void attn_av_kernel(const float* __restrict__ S, const float* __restrict__ V,
                    float* __restrict__ O)
{
    int bh = blockIdx.y;
    int b = bh >> 2, h = bh & 3;
    int m0 = blockIdx.x * 64;
    const float* Sb = S + (size_t)bh * SEQ * SEQ;

    __shared__ float As[16][68];
    __shared__ float Vs[16][96];

    int tid = threadIdx.x;
    int tx = tid & 15, ty = tid >> 4;
    int a_mi = tid >> 2;
    int a_k4 = (tid & 3) * 4;

    float acc[4][6];
#pragma unroll
    for (int i = 0; i < 4; ++i)
#pragma unroll
        for (int j = 0; j < 6; ++j) acc[i][j] = 0.f;

    for (int k0 = 0; k0 < SEQ; k0 += 16) {
        int gq = m0 + a_mi;
#pragma unroll
        for (int t = 0; t < 4; ++t) {
            int gk = k0 + a_k4 + t;
            As[a_k4 + t][a_mi] =
                (gq < SEQ && gk < SEQ) ? Sb[(size_t)gq * SEQ + gk] : 0.f;
        }
#pragma unroll
        for (int i = 0; i < 6; ++i) {
            int e = tid + i * 256;
            int kk = e / 96, n = e % 96;
            int gk = k0 + kk;
            Vs[kk][n] = (gk < SEQ)
                ? V[((size_t)b * SEQ + gk) * DMODEL + h * HDIM + n] : 0.f;
        }
        __syncthreads();
#pragma unroll
        for (int kk = 0; kk < 16; ++kk) {
            float bj[6];
#pragma unroll
            for (int j = 0; j < 6; ++j) bj[j] = Vs[kk][tx + 16 * j];
#pragma unroll
            for (int i = 0; i < 4; ++i) {
                float a = As[kk][ty * 4 + i];
#pragma unroll
                for (int j = 0; j < 6; ++j)
                    acc[i][j] = fmaf(a, bj[j], acc[i][j]);
            }
        }
        __syncthreads();
    }

#pragma unroll
    for (int i = 0; i < 4; ++i) {
        int q = m0 + ty * 4 + i;
        if (q >= SEQ) continue;
#pragma unroll
        for (int j = 0; j < 6; ++j)
            O[((size_t)b * SEQ + q) * DMODEL + h * HDIM + tx + 16 * j] = acc[i][j];
    }
}

// ---------------- final LN(cls row) + proj + loss ----------------
__global__ void final_kernel(const float* __restrict__ h,
                             const float* __restrict__ lnf_s, const float* __restrict__ lnf_b,
                             const float* __restrict__ pw, const float* __restrict__ pb,
                             const int* __restrict__ targets,
                             float* __restrict__ out, int out_size)
{
    int tid = threadIdx.x;
    __shared__ float losses[BATCH];
    if (tid < BATCH) {
        const float* xr = h + (size_t)tid * SEQ * DMODEL;  // cls row (t=0)
        float sum = 0.f;
        for (int d = 0; d < DMODEL; ++d) sum += xr[d];
        float mean = sum * (1.f / DMODEL);
        float sq = 0.f;
        for (int d = 0; d < DMODEL; ++d) {
            float dv = xr[d] - mean;
            sq += dv * dv;
        }
        float inv = rsqrtf(sq * (1.f / DMODEL) + 1e-5f);
        float l0 = pb[0], l1 = pb[1];
        for (int d = 0; d < DMODEL; ++d) {
            float nd = (xr[d] - mean) * inv * lnf_s[d] + lnf_b[d];
            l0 += nd * pw[d * NCLS + 0];
            l1 += nd * pw[d * NCLS + 1];
        }
        out[tid * 2 + 0] = l0;
        out[tid * 2 + 1] = l1;
        float mxl = fmaxf(l0, l1);
        float lse = mxl + logf(expf(l0 - mxl) + expf(l1 - mxl));
        int t = targets[tid];
        losses[tid] = lse - (t == 0 ? l0 : l1);
    }
    __syncthreads();
    if (tid == 0) {
        float s = 0.f;
        for (int i = 0; i < BATCH; ++i) s += losses[i];
        if (out_size > BATCH * NCLS) out[BATCH * NCLS] = s * (1.f / BATCH);
    }
}

// ---------------- launch ----------------
extern "C" void kernel_launch(void* const* d_in, const int* in_sizes, int n_in,
                              void* d_out, int out_size)
{
    const float* x        = (const float*)d_in[0];
    const int*   targets  = (const int*)  d_in[1];
    const float* conv_w   = (const float*)d_in[2];
    const float* conv_b   = (const float*)d_in[3];
    const float* cls_tok  = (const float*)d_in[4];
    const float* pos_emb  = (const float*)d_in[5];
    const float* ln1_s    = (const float*)d_in[6];
    const float* ln1_b    = (const float*)d_in[7];
    const float* ln2_s    = (const float*)d_in[8];
    const float* ln2_b    = (const float*)d_in[9];
    const float* wq       = (const float*)d_in[10];
    const float* wk       = (const float*)d_in[11];
    const float* wv       = (const float*)d_in[12];
    const float* wo       = (const float*)d_in[13];
    const float* bo       = (const float*)d_in[14];
    const float* w1       = (const float*)d_in[15];
    const float* b1       = (const float*)d_in[16];
    const float* w2       = (const float*)d_in[17];
    const float* b2       = (const float*)d_in[18];
    const float* lnf_s    = (const float*)d_in[19];
    const float* lnf_b    = (const float*)d_in[20];
    const float* proj_w   = (const float*)d_in[21];
    const float* proj_b   = (const float*)d_in[22];

    float *h, *hn, *q, *k, *v, *vals, *f, *s;
    cudaGetSymbolAddress((void**)&h,    g_h);
    cudaGetSymbolAddress((void**)&hn,   g_hn);
    cudaGetSymbolAddress((void**)&q,    g_q);
    cudaGetSymbolAddress((void**)&k,    g_k);
    cudaGetSymbolAddress((void**)&v,    g_v);
    cudaGetSymbolAddress((void**)&vals, g_vals);
    cudaGetSymbolAddress((void**)&f,    g_f);
    cudaGetSymbolAddress((void**)&s,    g_s);

    // patch embedding + pos emb + cls row
    patch_embed_kernel<<<dim3(3, 128), 256>>>(x, conv_w, conv_b, pos_emb, h);
    cls_kernel<<<BATCH, DMODEL>>>(cls_tok, pos_emb, h);

    const int MT = (MROWS + GBM - 1) / GBM;  // 129
    for (int i = 0; i < NBLOCKS; ++i) {
        const float* wqi = wq + (size_t)i * DMODEL * DMODEL;
        const float* wki = wk + (size_t)i * DMODEL * DMODEL;
        const float* wvi = wv + (size_t)i * DMODEL * DMODEL;
        const float* woi = wo + (size_t)i * DMODEL * DMODEL;
        const float* w1i = w1 + (size_t)i * DMODEL * FFDIM;
        const float* w2i = w2 + (size_t)i * FFDIM * DMODEL;

        ln_kernel<<<MROWS, 128>>>(h, hn, ln1_s + i * DMODEL, ln1_b + i * DMODEL);

        sgemm_kernel<0><<<dim3(3, MT), 256>>>(hn, wqi, q, nullptr, MROWS, DMODEL, DMODEL);
        sgemm_kernel<0><<<dim3(3, MT), 256>>>(hn, wki, k, nullptr, MROWS, DMODEL, DMODEL);
        sgemm_kernel<0><<<dim3(3, MT), 256>>>(hn, wvi, v, nullptr, MROWS, DMODEL, DMODEL);

        scores_kernel<<<dim3(17, 17, BATCH * NHEADS), 256>>>(q, k, s);
        softmax_kernel<<<BATCH * NHEADS * SEQ, 256>>>(s);
        attn_av_kernel<<<dim3(17, BATCH * NHEADS), 256>>>(s, v, vals);

        sgemm_kernel<3><<<dim3(3, MT), 256>>>(vals, woi, h, bo + i * DMODEL,
                                              MROWS, DMODEL, DMODEL);

        ln_kernel<<<MROWS, 128>>>(h, hn, ln2_s + i * DMODEL, ln2_b + i * DMODEL);
        sgemm_kernel<2><<<dim3(12, MT), 256>>>(hn, w1i, f, b1 + i * FFDIM,
                                               MROWS, FFDIM, DMODEL);
        sgemm_kernel<3><<<dim3(3, MT), 256>>>(f, w2i, h, b2 + i * DMODEL,
                                              MROWS, DMODEL, FFDIM);
    }

    final_kernel<<<1, 32>>>(h, lnf_s, lnf_b, proj_w, proj_b, targets,
                            (float*)d_out, out_size);
}

// round 2
// speedup vs baseline: 2.1597x; 2.1597x over previous
#include <cuda_runtime.h>
#include <math.h>
#include <stdint.h>

// ---------------- problem constants ----------------
#define BATCH 16
#define IMG 512
#define PATCH 16
#define CIN 3
#define DMODEL 384
#define NHEADS 4
#define HDIM 96
#define NBLOCKS 3
#define NCLS 2
#define NPATCH 1024
#define SEQ 1025
#define SP 1028               // padded row stride for attention matrices (float4-aligned)
#define FFDIM 1536
#define MROWS (BATCH * SEQ)   // 16400
#define BH (BATCH * NHEADS)   // 64

// ---------------- scratch ----------------
__device__ float g_h   [(size_t)MROWS * DMODEL];
__device__ float g_hn  [(size_t)MROWS * DMODEL];
__device__ float g_q   [(size_t)MROWS * DMODEL];
__device__ float g_k   [(size_t)MROWS * DMODEL];
__device__ float g_v   [(size_t)MROWS * DMODEL];
__device__ float g_vals[(size_t)MROWS * DMODEL];
__device__ float g_f   [(size_t)MROWS * FFDIM];
__device__ float g_s   [(size_t)BH * SEQ * SP + 256];   // scores / probs (padded rows)
__device__ float g_kt  [(size_t)BH * HDIM * SP + 256];  // K^T per head: [bh][d][t]
__device__ float g_qq  [(size_t)BH * SEQ];
__device__ float g_kk  [(size_t)BH * SEQ];
__device__ float g_wt  [(size_t)CIN * PATCH * PATCH * DMODEL];  // conv_w transposed [768][384]

// ---------------- tf32 helpers ----------------
__device__ __forceinline__ float cvt_tf32(float x) {
    uint32_t u;
    asm("cvt.rna.tf32.f32 %0, %1;" : "=r"(u) : "f"(x));
    return __uint_as_float(u);
}

__device__ __forceinline__ void mma8(float* d, const uint32_t* a, const uint32_t* b) {
    asm volatile(
        "mma.sync.aligned.m16n8k8.row.col.f32.tf32.tf32.f32 "
        "{%0,%1,%2,%3}, {%4,%5,%6,%7}, {%8,%9}, {%0,%1,%2,%3};"
        : "+f"(d[0]), "+f"(d[1]), "+f"(d[2]), "+f"(d[3])
        : "r"(a[0]), "r"(a[1]), "r"(a[2]), "r"(a[3]), "r"(b[0]), "r"(b[1]));
}

// epilogue modes
#define E_NONE  0
#define E_RELU  2
#define E_RES   3
#define E_SCORE 4
#define E_PATCH 5

// addressing modes
// 0: plain (A,B,C as given, z unused)
// 1: scores  A = q (per-bh head slice), B = kT (linear per z), C = s (linear per z)
// 2: AV      A = s (linear per z),      B = v (per-bh head slice), C = vals (head slice)
// 3: patch   A = x (im2col gather),     B = wt, C = h (patch rows)

// ---------------- unified TF32 GEMM ----------------
// BM=128, BK=16, 256 threads = 8 warps (2 m x 4 n). Warp tile: 64 x (BN/4).
template <int EPI, int BN, int ADDR>
__global__ __launch_bounds__(256, 2)
void gemm_tf32(const float* __restrict__ Ab, int lda,
               const float* __restrict__ Bb, int ldb,
               float* __restrict__ Cb, int ldc,
               const float* __restrict__ bias,   // bias, or kk for E_SCORE
               const float* __restrict__ aux,    // pos_emb for E_PATCH, qq for E_SCORE
               int M, int N, int K)
{
    constexpr int BM = 128, BK = 16;
    constexpr int NT = BN / 32;            // n-tiles (8 wide) per warp
    __shared__ float As[BM][BK + 4];       // [m][k], stride 20 floats
    __shared__ float Bs[BK][BN + 8];       // [k][n], stride BN+8 floats

    const int tid  = threadIdx.x;
    const int lane = tid & 31;
    const int w    = tid >> 5;
    const int wm   = (w >> 2) * 64;
    const int wn   = (w & 3) * (NT * 8);
    const int m0   = blockIdx.y * BM;
    const int n0   = blockIdx.x * BN;
    const int z    = blockIdx.z;

    const float* A = Ab;
    const float* B = Bb;
    float* C = Cb;
    const float* qqz = aux;
    const float* kkz = bias;
    if (ADDR == 1) {
        int b = z >> 2, hh = z & 3;
        A = Ab + ((size_t)b * SEQ) * DMODEL + hh * HDIM;
        B = Bb + (size_t)z * HDIM * SP;
        C = Cb + (size_t)z * SEQ * SP;
        qqz = aux + (size_t)z * SEQ;
        kkz = bias + (size_t)z * SEQ;
    } else if (ADDR == 2) {
        int b = z >> 2, hh = z & 3;
        A = Ab + (size_t)z * SEQ * SP;
        B = Bb + ((size_t)b * SEQ) * DMODEL + hh * HDIM;
        C = Cb + ((size_t)b * SEQ) * DMODEL + hh * HDIM;
    }

    // loader indices
    const int arow = tid >> 1;            // 0..127
    const int acol = (tid & 1) * 8;       // 0 or 8
    const int brow = tid >> 4;            // 0..15
    const int bcol = tid & 15;            // float4 index base

    float acc[4][NT][4];
#pragma unroll
    for (int mt = 0; mt < 4; ++mt)
#pragma unroll
        for (int nt = 0; nt < NT; ++nt)
#pragma unroll
            for (int e = 0; e < 4; ++e) acc[mt][nt][e] = 0.f;

    float pa[8];
    float pb[2][8];

    // ---- first tile load ----
    {
        const int k0 = 0;
        // A
        int gm = m0 + arow;
        const float* ap;
        bool mok;
        if (ADDR == 3) {
            int bb = gm >> 10, pix = gm & 1023, hp = pix >> 5, wp = pix & 31;
            int kb = k0 + acol;
            int c = kb >> 8, r = (kb >> 4) & 15, qc = kb & 15;
            ap = Ab + (((size_t)(bb * CIN + c) * IMG + hp * PATCH + r) * IMG + wp * PATCH + qc);
            mok = true;
        } else {
            ap = A + (size_t)gm * lda + k0 + acol;
            mok = (gm < M);
        }
        if (mok) {
            float4 v0 = *(const float4*)ap;
            float4 v1 = *(const float4*)(ap + 4);
            pa[0] = v0.x; pa[1] = v0.y; pa[2] = v0.z; pa[3] = v0.w;
            pa[4] = v1.x; pa[5] = v1.y; pa[6] = v1.z; pa[7] = v1.w;
        } else {
#pragma unroll
            for (int i = 0; i < 8; ++i) pa[i] = 0.f;
        }
        // B
#pragma unroll
        for (int i = 0; i < 2; ++i) {
            int c4 = bcol + i * 16;
            int gk = k0 + brow;
            bool ok = (gk < K) && (BN == 128 || c4 < BN / 4);
            if (ok) {
                float4 v = *(const float4*)(B + (size_t)gk * ldb + n0 + c4 * 4);
                pb[i][0] = v.x; pb[i][1] = v.y; pb[i][2] = v.z; pb[i][3] = v.w;
            } else {
                pb[i][0] = pb[i][1] = pb[i][2] = pb[i][3] = 0.f;
            }
        }
    }

    int k0 = 0;
    for (;;) {
        // ---- STS (with tf32 rounding) ----
#pragma unroll
        for (int i = 0; i < 8; ++i) As[arow][acol + i] = cvt_tf32(pa[i]);
#pragma unroll
        for (int i = 0; i < 2; ++i) {
            int c4 = bcol + i * 16;
            if (BN == 128 || c4 < BN / 4) {
                float4 v;
                v.x = cvt_tf32(pb[i][0]); v.y = cvt_tf32(pb[i][1]);
                v.z = cvt_tf32(pb[i][2]); v.w = cvt_tf32(pb[i][3]);
                *(float4*)&Bs[brow][c4 * 4] = v;
            }
        }
        __syncthreads();

        const int knext = k0 + BK;
        const bool more = (knext < K);
        if (more) {
            // ---- prefetch next tile into registers ----
            int gm = m0 + arow;
            const float* ap;
            bool mok;
            if (ADDR == 3) {
                int bb = gm >> 10, pix = gm & 1023, hp = pix >> 5, wp = pix & 31;
                int kb = knext + acol;
                int c = kb >> 8, r = (kb >> 4) & 15, qc = kb & 15;
                ap = Ab + (((size_t)(bb * CIN + c) * IMG + hp * PATCH + r) * IMG + wp * PATCH + qc);
                mok = true;
            } else {
                ap = A + (size_t)gm * lda + knext + acol;
                mok = (gm < M);
            }
            if (mok) {
                float4 v0 = *(const float4*)ap;
                float4 v1 = *(const float4*)(ap + 4);
                pa[0] = v0.x; pa[1] = v0.y; pa[2] = v0.z; pa[3] = v0.w;
                pa[4] = v1.x; pa[5] = v1.y; pa[6] = v1.z; pa[7] = v1.w;
            } else {
#pragma unroll
                for (int i = 0; i < 8; ++i) pa[i] = 0.f;
            }
#pragma unroll
            for (int i = 0; i < 2; ++i) {
                int c4 = bcol + i * 16;
                int gk = knext + brow;
                bool ok = (gk < K) && (BN == 128 || c4 < BN / 4);
                if (ok) {
                    float4 v = *(const float4*)(B + (size_t)gk * ldb + n0 + c4 * 4);
                    pb[i][0] = v.x; pb[i][1] = v.y; pb[i][2] = v.z; pb[i][3] = v.w;
                } else {
                    pb[i][0] = pb[i][1] = pb[i][2] = pb[i][3] = 0.f;
                }
            }
        }

        // ---- compute: 2 k-steps of 8 ----
#pragma unroll
        for (int ks = 0; ks < BK; ks += 8) {
            uint32_t af[4][4];
            const int kk_ = ks + (lane & 3);
            const int gmr = lane >> 2;
#pragma unroll
            for (int mt = 0; mt < 4; ++mt) {
                int mm = wm + mt * 16 + gmr;
                af[mt][0] = __float_as_uint(As[mm][kk_]);
                af[mt][1] = __float_as_uint(As[mm + 8][kk_]);
                af[mt][2] = __float_as_uint(As[mm][kk_ + 4]);
                af[mt][3] = __float_as_uint(As[mm + 8][kk_ + 4]);
            }
#pragma unroll
            for (int nt = 0; nt < NT; ++nt) {
                uint32_t bf[2];
                int nn = wn + nt * 8 + gmr;
                bf[0] = __float_as_uint(Bs[kk_][nn]);
                bf[1] = __float_as_uint(Bs[kk_ + 4][nn]);
#pragma unroll
                for (int mt = 0; mt < 4; ++mt)
                    mma8(acc[mt][nt], af[mt], bf);
            }
        }
        __syncthreads();
        if (!more) break;
        k0 = knext;
    }

    // ---- epilogue ----
#pragma unroll
    for (int mt = 0; mt < 4; ++mt) {
#pragma unroll
        for (int nt = 0; nt < NT; ++nt) {
#pragma unroll
            for (int e = 0; e < 4; ++e) {
                int m = m0 + wm + mt * 16 + (lane >> 2) + ((e >= 2) ? 8 : 0);
                int n = n0 + wn + nt * 8 + (lane & 3) * 2 + (e & 1);
                if (m >= M || n >= N) continue;
                float v = acc[mt][nt][e];
                size_t idx;
                if (EPI == E_PATCH) {
                    int bb = m >> 10, np = m & 1023;
                    idx = ((size_t)bb * SEQ + 1 + np) * DMODEL + n;
                    v += bias[n] + aux[(size_t)(1 + np) * DMODEL + n];
                } else {
                    idx = (size_t)m * ldc + n;
                    if (EPI == E_RELU) { v += bias[n]; v = fmaxf(v, 0.f); }
                    else if (EPI == E_RES) { v += bias[n] + C[idx]; }
                    else if (EPI == E_SCORE) {
                        v = sqrtf(fmaxf(qqz[m] + kkz[n] - 2.f * v, 0.f))
                            * 0.10206207261596577f;
                    }
                }
                C[idx] = v;
            }
        }
    }
}

// ---------------- conv weight transpose: cw[N=384][K=768] -> wt[K][N] ----------------
__global__ void transpose_w_kernel(const float* __restrict__ cw, float* __restrict__ wt)
{
    __shared__ float t[32][33];
    int k0 = blockIdx.x * 32, n0 = blockIdx.y * 32;
    int tx = threadIdx.x, ty = threadIdx.y;
    for (int i = ty; i < 32; i += 8)
        t[i][tx] = cw[(size_t)(n0 + i) * (CIN * PATCH * PATCH) + k0 + tx];
    __syncthreads();
    for (int i = ty; i < 32; i += 8)
        wt[(size_t)(k0 + i) * DMODEL + n0 + tx] = t[tx][i];
}

// ---------------- K^T per head: kT[bh][d][t] ----------------
__global__ void transpose_k_kernel(const float* __restrict__ k, float* __restrict__ kT)
{
    __shared__ float t[32][33];
    int z = blockIdx.z;
    int b = z >> 2, h = z & 3;
    int t0 = blockIdx.x * 32, d0 = blockIdx.y * 32;
    int tx = threadIdx.x, ty = threadIdx.y;
    for (int i = ty; i < 32; i += 8) {
        int tt = t0 + i;
        t[i][tx] = (tt < SEQ)
            ? k[((size_t)b * SEQ + tt) * DMODEL + h * HDIM + d0 + tx] : 0.f;
    }
    __syncthreads();
    for (int i = ty; i < 32; i += 8) {
        int tt = t0 + tx;
        if (tt < SEQ)
            kT[((size_t)z * HDIM + d0 + i) * SP + tt] = t[tx][i];
    }
}

// ---------------- per-row |q|^2 and |k|^2 per head ----------------
__global__ void sumsq_kernel(const float* __restrict__ q, const float* __restrict__ k,
                             float* __restrict__ qq, float* __restrict__ kk)
{
    int gw = (blockIdx.x * blockDim.x + threadIdx.x) >> 5;
    int lane = threadIdx.x & 31;
    if (gw >= BH * SEQ) return;
    int z = gw / SEQ, t = gw % SEQ;
    int b = z >> 2, h = z & 3;
    const float* qr = q + ((size_t)b * SEQ + t) * DMODEL + h * HDIM;
    const float* kr = k + ((size_t)b * SEQ + t) * DMODEL + h * HDIM;
    float sq = 0.f, sk = 0.f;
#pragma unroll
    for (int i = 0; i < 3; ++i) {
        float a = qr[lane + 32 * i]; sq += a * a;
        float c = kr[lane + 32 * i]; sk += c * c;
    }
#pragma unroll
    for (int o = 16; o > 0; o >>= 1) {
        sq += __shfl_down_sync(0xffffffffu, sq, o);
        sk += __shfl_down_sync(0xffffffffu, sk, o);
    }
    if (lane == 0) { qq[gw] = sq; kk[gw] = sk; }
}

// ---------------- cls row ----------------
__global__ void cls_kernel(const float* __restrict__ cls_token,
                           const float* __restrict__ pos, float* __restrict__ h)
{
    int b = blockIdx.x, d = threadIdx.x;
    h[(size_t)b * SEQ * DMODEL + d] = cls_token[d] + pos[d];
}

// ---------------- LayerNorm over D=384 ----------------
__global__ void ln_kernel(const float* __restrict__ x, float* __restrict__ y,
                          const float* __restrict__ s, const float* __restrict__ bb)
{
    int row = blockIdx.x;
    const float* xr = x + (size_t)row * DMODEL;
    float* yr = y + (size_t)row * DMODEL;
    int tid = threadIdx.x;  // 128

    float v0 = xr[tid], v1 = xr[tid + 128], v2 = xr[tid + 256];

    __shared__ float red[128];
    red[tid] = v0 + v1 + v2;
    __syncthreads();
#pragma unroll
    for (int o = 64; o > 0; o >>= 1) {
        if (tid < o) red[tid] += red[tid + o];
        __syncthreads();
    }
    float mean = red[0] * (1.f / DMODEL);
    __syncthreads();

    float d0 = v0 - mean, d1 = v1 - mean, d2 = v2 - mean;
    red[tid] = d0 * d0 + d1 * d1 + d2 * d2;
    __syncthreads();
#pragma unroll
    for (int o = 64; o > 0; o >>= 1) {
        if (tid < o) red[tid] += red[tid + o];
        __syncthreads();
    }
    float var = red[0] * (1.f / DMODEL);
    float inv = rsqrtf(var + 1e-5f);

    yr[tid]       = d0 * inv * s[tid]       + bb[tid];
    yr[tid + 128] = d1 * inv * s[tid + 128] + bb[tid + 128];
    yr[tid + 256] = d2 * inv * s[tid + 256] + bb[tid + 256];
}

// ---------------- row softmax over SEQ (rows padded to SP) ----------------
__global__ void softmax_kernel(float* __restrict__ S)
{
    float* r = S + (size_t)blockIdx.x * SP;
    int tid = threadIdx.x;  // 256
    float v[5];
    float mx = -1e30f;
#pragma unroll
    for (int i = 0; i < 5; ++i) {
        int idx = tid + i * 256;
        if (idx < SEQ) { v[i] = r[idx]; mx = fmaxf(mx, v[i]); }
        else v[i] = -1e30f;
    }
    __shared__ float red[256];
    red[tid] = mx;
    __syncthreads();
#pragma unroll
    for (int o = 128; o > 0; o >>= 1) {
        if (tid < o) red[tid] = fmaxf(red[tid], red[tid + o]);
        __syncthreads();
    }
    mx = red[0];
    __syncthreads();

    float sum = 0.f;
#pragma unroll
    for (int i = 0; i < 5; ++i) {
        int idx = tid + i * 256;
        if (idx < SEQ) { v[i] = __expf(v[i] - mx); sum += v[i]; }
    }
    red[tid] = sum;
    __syncthreads();
#pragma unroll
    for (int o = 128; o > 0; o >>= 1) {
        if (tid < o) red[tid] += red[tid + o];
        __syncthreads();
    }
    float inv = 1.f / red[0];
#pragma unroll
    for (int i = 0; i < 5; ++i) {
        int idx = tid + i * 256;
        if (idx < SEQ) r[idx] = v[i] * inv;
    }
}

// ---------------- final LN(cls) + proj + loss ----------------
__global__ void final_kernel(const float* __restrict__ h,
                             const float* __restrict__ lnf_s, const float* __restrict__ lnf_b,
                             const float* __restrict__ pw, const float* __restrict__ pb,
                             const int* __restrict__ targets,
                             float* __restrict__ out, int out_size)
{
    int tid = threadIdx.x;
    __shared__ float losses[BATCH];
    if (tid < BATCH) {
        const float* xr = h + (size_t)tid * SEQ * DMODEL;
        float sum = 0.f;
        for (int d = 0; d < DMODEL; ++d) sum += xr[d];
        float mean = sum * (1.f / DMODEL);
        float sq = 0.f;
        for (int d = 0; d < DMODEL; ++d) {
            float dv = xr[d] - mean;
            sq += dv * dv;
        }
        float inv = rsqrtf(sq * (1.f / DMODEL) + 1e-5f);
        float l0 = pb[0], l1 = pb[1];
        for (int d = 0; d < DMODEL; ++d) {
            float nd = (xr[d] - mean) * inv * lnf_s[d] + lnf_b[d];
            l0 += nd * pw[d * NCLS + 0];
            l1 += nd * pw[d * NCLS + 1];
        }
        out[tid * 2 + 0] = l0;
        out[tid * 2 + 1] = l1;
        float mxl = fmaxf(l0, l1);
        float lse = mxl + logf(expf(l0 - mxl) + expf(l1 - mxl));
        int t = targets[tid];
        losses[tid] = lse - (t == 0 ? l0 : l1);
    }
    __syncthreads();
    if (tid == 0) {
        float s = 0.f;
        for (int i = 0; i < BATCH; ++i) s += losses[i];
        if (out_size > BATCH * NCLS) out[BATCH * NCLS] = s * (1.f / BATCH);
    }
}

// ---------------- launch ----------------
extern "C" void kernel_launch(void* const* d_in, const int* in_sizes, int n_in,
                              void* d_out, int out_size)
{
    const float* x       = (const float*)d_in[0];
    const int*   targets = (const int*)  d_in[1];
    const float* conv_w  = (const float*)d_in[2];
    const float* conv_b  = (const float*)d_in[3];
    const float* cls_tok = (const float*)d_in[4];
    const float* pos_emb = (const float*)d_in[5];
    const float* ln1_s   = (const float*)d_in[6];
    const float* ln1_b   = (const float*)d_in[7];
    const float* ln2_s   = (const float*)d_in[8];
    const float* ln2_b   = (const float*)d_in[9];
    const float* wq      = (const float*)d_in[10];
    const float* wk      = (const float*)d_in[11];
    const float* wv      = (const float*)d_in[12];
    const float* wo      = (const float*)d_in[13];
    const float* bo      = (const float*)d_in[14];
    const float* w1      = (const float*)d_in[15];
    const float* b1      = (const float*)d_in[16];
    const float* w2      = (const float*)d_in[17];
    const float* b2      = (const float*)d_in[18];
    const float* lnf_s   = (const float*)d_in[19];
    const float* lnf_b   = (const float*)d_in[20];
    const float* proj_w  = (const float*)d_in[21];
    const float* proj_b  = (const float*)d_in[22];

    float *h, *hn, *q, *k, *v, *vals, *f, *s, *kt, *qq, *kk, *wt;
    cudaGetSymbolAddress((void**)&h,    g_h);
    cudaGetSymbolAddress((void**)&hn,   g_hn);
    cudaGetSymbolAddress((void**)&q,    g_q);
    cudaGetSymbolAddress((void**)&k,    g_k);
    cudaGetSymbolAddress((void**)&v,    g_v);
    cudaGetSymbolAddress((void**)&vals, g_vals);
    cudaGetSymbolAddress((void**)&f,    g_f);
    cudaGetSymbolAddress((void**)&s,    g_s);
    cudaGetSymbolAddress((void**)&kt,   g_kt);
    cudaGetSymbolAddress((void**)&qq,   g_qq);
    cudaGetSymbolAddress((void**)&kk,   g_kk);
    cudaGetSymbolAddress((void**)&wt,   g_wt);

    // patch embedding (im2col tf32 GEMM) + cls row
    transpose_w_kernel<<<dim3(24, 12), dim3(32, 8)>>>(conv_w, wt);
    gemm_tf32<E_PATCH, 128, 3><<<dim3(3, 128, 1), 256>>>(
        x, 0, wt, DMODEL, h, DMODEL, conv_b, pos_emb,
        BATCH * NPATCH, DMODEL, CIN * PATCH * PATCH);
    cls_kernel<<<BATCH, DMODEL>>>(cls_tok, pos_emb, h);

    const int MT = (MROWS + 127) / 128;  // 129
    for (int i = 0; i < NBLOCKS; ++i) {
        const float* wqi = wq + (size_t)i * DMODEL * DMODEL;
        const float* wki = wk + (size_t)i * DMODEL * DMODEL;
        const float* wvi = wv + (size_t)i * DMODEL * DMODEL;
        const float* woi = wo + (size_t)i * DMODEL * DMODEL;
        const float* w1i = w1 + (size_t)i * DMODEL * FFDIM;
        const float* w2i = w2 + (size_t)i * FFDIM * DMODEL;

        ln_kernel<<<MROWS, 128>>>(h, hn, ln1_s + i * DMODEL, ln1_b + i * DMODEL);

        gemm_tf32<E_NONE, 128, 0><<<dim3(3, MT, 1), 256>>>(
            hn, DMODEL, wqi, DMODEL, q, DMODEL, nullptr, nullptr, MROWS, DMODEL, DMODEL);
        gemm_tf32<E_NONE, 128, 0><<<dim3(3, MT, 1), 256>>>(
            hn, DMODEL, wki, DMODEL, k, DMODEL, nullptr, nullptr, MROWS, DMODEL, DMODEL);
        gemm_tf32<E_NONE, 128, 0><<<dim3(3, MT, 1), 256>>>(
            hn, DMODEL, wvi, DMODEL, v, DMODEL, nullptr, nullptr, MROWS, DMODEL, DMODEL);

        transpose_k_kernel<<<dim3(33, 3, BH), dim3(32, 8)>>>(k, kt);
        sumsq_kernel<<<(BH * SEQ + 7) / 8, 256>>>(q, k, qq, kk);

        gemm_tf32<E_SCORE, 128, 1><<<dim3(9, 9, BH), 256>>>(
            q, DMODEL, kt, SP, s, SP, kk, qq, SEQ, SEQ, HDIM);

        softmax_kernel<<<BH * SEQ, 256>>>(s);

        gemm_tf32<E_NONE, 96, 2><<<dim3(1, 9, BH), 256>>>(
            s, SP, v, DMODEL, vals, DMODEL, nullptr, nullptr, SEQ, HDIM, SEQ);

        gemm_tf32<E_RES, 128, 0><<<dim3(3, MT, 1), 256>>>(
            vals, DMODEL, woi, DMODEL, h, DMODEL, bo + i * DMODEL, nullptr,
            MROWS, DMODEL, DMODEL);

        ln_kernel<<<MROWS, 128>>>(h, hn, ln2_s + i * DMODEL, ln2_b + i * DMODEL);

        gemm_tf32<E_RELU, 128, 0><<<dim3(12, MT, 1), 256>>>(
            hn, DMODEL, w1i, FFDIM, f, FFDIM, b1 + i * FFDIM, nullptr,
            MROWS, FFDIM, DMODEL);

        gemm_tf32<E_RES, 128, 0><<<dim3(3, MT, 1), 256>>>(
            f, FFDIM, w2i, DMODEL, h, DMODEL, b2 + i * DMODEL, nullptr,
            MROWS, DMODEL, FFDIM);
    }

    final_kernel<<<1, 32>>>(h, lnf_s, lnf_b, proj_w, proj_b, targets,
                            (float*)d_out, out_size);
}

// round 3
// speedup vs baseline: 2.6850x; 1.2432x over previous
#include <cuda_runtime.h>
#include <math.h>
#include <stdint.h>

// ---------------- problem constants ----------------
#define BATCH 16
#define IMG 512
#define PATCH 16
#define CIN 3
#define DMODEL 384
#define NHEADS 4
#define HDIM 96
#define NBLOCKS 3
#define NCLS 2
#define NPATCH 1024
#define SEQ 1025
#define FFDIM 1536
#define MROWS (BATCH * SEQ)   // 16400
#define BH (BATCH * NHEADS)   // 64
#define SCALE_ATT 0.10206207261596577f   // 1/sqrt(96)

// ---------------- scratch ----------------
__device__ float g_h   [(size_t)MROWS * DMODEL];
__device__ float g_hn  [(size_t)MROWS * DMODEL];
__device__ float g_q   [(size_t)MROWS * DMODEL];
__device__ float g_k   [(size_t)MROWS * DMODEL];
__device__ float g_v   [(size_t)MROWS * DMODEL];
__device__ float g_vals[(size_t)MROWS * DMODEL];
__device__ float g_f   [(size_t)MROWS * FFDIM];
__device__ float g_qq  [(size_t)BH * SEQ];
__device__ float g_kk  [(size_t)BH * SEQ];
__device__ float g_wt  [(size_t)CIN * PATCH * PATCH * DMODEL];

// ---------------- tf32 helpers ----------------
__device__ __forceinline__ float cvt_tf32(float x) {
    uint32_t u;
    asm("cvt.rna.tf32.f32 %0, %1;" : "=r"(u) : "f"(x));
    return __uint_as_float(u);
}
__device__ __forceinline__ uint32_t tf32u(float x) {
    uint32_t u;
    asm("cvt.rna.tf32.f32 %0, %1;" : "=r"(u) : "f"(x));
    return u;
}

__device__ __forceinline__ void mma8(float* d, const uint32_t* a, const uint32_t* b) {
    asm volatile(
        "mma.sync.aligned.m16n8k8.row.col.f32.tf32.tf32.f32 "
        "{%0,%1,%2,%3}, {%4,%5,%6,%7}, {%8,%9}, {%0,%1,%2,%3};"
        : "+f"(d[0]), "+f"(d[1]), "+f"(d[2]), "+f"(d[3])
        : "r"(a[0]), "r"(a[1]), "r"(a[2]), "r"(a[3]), "r"(b[0]), "r"(b[1]));
}

// epilogue modes
#define E_NONE  0
#define E_RELU  2
#define E_RES   3
#define E_PATCH 5
// addressing modes: 0 plain, 3 patch-im2col, 4 fused QKV

// ---------------- unified TF32 GEMM ----------------
template <int EPI, int BN, int ADDR>
__global__ __launch_bounds__(256, 2)
void gemm_tf32(const float* __restrict__ Ab, int lda,
               const float* __restrict__ Bb, int ldb,
               float* __restrict__ Cb, int ldc,
               const float* __restrict__ bias,
               const float* __restrict__ aux,    // pos_emb for E_PATCH
               const float* __restrict__ Bx2, const float* __restrict__ Bx3,
               float* __restrict__ Cx2, float* __restrict__ Cx3,
               int M, int N, int K)
{
    constexpr int BM = 128, BK = 16;
    constexpr int NT = BN / 32;
    __shared__ float As[BM][BK + 4];
    __shared__ float Bs[BK][BN + 8];

    const int tid  = threadIdx.x;
    const int lane = tid & 31;
    const int w    = tid >> 5;
    const int wm   = (w >> 2) * 64;
    const int wn   = (w & 3) * (NT * 8);
    const int m0   = blockIdx.y * BM;
    int n0         = blockIdx.x * BN;

    const float* A = Ab;
    const float* B = Bb;
    float* C = Cb;
    if (ADDR == 4) {
        int mat = blockIdx.x / 3;
        n0 = (blockIdx.x % 3) * BN;
        B = (mat == 0) ? Bb : (mat == 1) ? Bx2 : Bx3;
        C = (mat == 0) ? Cb : (mat == 1) ? Cx2 : Cx3;
    }

    const int arow = tid >> 1;
    const int acol = (tid & 1) * 8;
    const int brow = tid >> 4;
    const int bcol = tid & 15;

    float acc[4][NT][4];
#pragma unroll
    for (int mt = 0; mt < 4; ++mt)
#pragma unroll
        for (int nt = 0; nt < NT; ++nt)
#pragma unroll
            for (int e = 0; e < 4; ++e) acc[mt][nt][e] = 0.f;

    float pa[8];
    float pb[2][8];

    // ---- first tile load ----
    {
        int gm = m0 + arow;
        const float* ap;
        bool mok;
        if (ADDR == 3) {
            int bb = gm >> 10, pix = gm & 1023, hp = pix >> 5, wp = pix & 31;
            int kb = acol;
            int c = kb >> 8, r = (kb >> 4) & 15, qc = kb & 15;
            ap = Ab + (((size_t)(bb * CIN + c) * IMG + hp * PATCH + r) * IMG + wp * PATCH + qc);
            mok = true;
        } else {
            ap = A + (size_t)gm * lda + acol;
            mok = (gm < M);
        }
        if (mok) {
            float4 v0 = *(const float4*)ap;
            float4 v1 = *(const float4*)(ap + 4);
            pa[0] = v0.x; pa[1] = v0.y; pa[2] = v0.z; pa[3] = v0.w;
            pa[4] = v1.x; pa[5] = v1.y; pa[6] = v1.z; pa[7] = v1.w;
        } else {
#pragma unroll
            for (int i = 0; i < 8; ++i) pa[i] = 0.f;
        }
#pragma unroll
        for (int i = 0; i < 2; ++i) {
            int c4 = bcol + i * 16;
            bool ok = (brow < K) && (BN == 128 || c4 < BN / 4);
            if (ok) {
                float4 v = *(const float4*)(B + (size_t)brow * ldb + n0 + c4 * 4);
                pb[i][0] = v.x; pb[i][1] = v.y; pb[i][2] = v.z; pb[i][3] = v.w;
            } else {
                pb[i][0] = pb[i][1] = pb[i][2] = pb[i][3] = 0.f;
            }
        }
    }

    int k0 = 0;
    for (;;) {
#pragma unroll
        for (int i = 0; i < 8; ++i) As[arow][acol + i] = cvt_tf32(pa[i]);
#pragma unroll
        for (int i = 0; i < 2; ++i) {
            int c4 = bcol + i * 16;
            if (BN == 128 || c4 < BN / 4) {
                float4 v;
                v.x = cvt_tf32(pb[i][0]); v.y = cvt_tf32(pb[i][1]);
                v.z = cvt_tf32(pb[i][2]); v.w = cvt_tf32(pb[i][3]);
                *(float4*)&Bs[brow][c4 * 4] = v;
            }
        }
        __syncthreads();

        const int knext = k0 + BK;
        const bool more = (knext < K);
        if (more) {
            int gm = m0 + arow;
            const float* ap;
            bool mok;
            if (ADDR == 3) {
                int bb = gm >> 10, pix = gm & 1023, hp = pix >> 5, wp = pix & 31;
                int kb = knext + acol;
                int c = kb >> 8, r = (kb >> 4) & 15, qc = kb & 15;
                ap = Ab + (((size_t)(bb * CIN + c) * IMG + hp * PATCH + r) * IMG + wp * PATCH + qc);
                mok = true;
            } else {
                ap = A + (size_t)gm * lda + knext + acol;
                mok = (gm < M);
            }
            if (mok) {
                float4 v0 = *(const float4*)ap;
                float4 v1 = *(const float4*)(ap + 4);
                pa[0] = v0.x; pa[1] = v0.y; pa[2] = v0.z; pa[3] = v0.w;
                pa[4] = v1.x; pa[5] = v1.y; pa[6] = v1.z; pa[7] = v1.w;
            } else {
#pragma unroll
                for (int i = 0; i < 8; ++i) pa[i] = 0.f;
            }
#pragma unroll
            for (int i = 0; i < 2; ++i) {
                int c4 = bcol + i * 16;
                int gk = knext + brow;
                bool ok = (gk < K) && (BN == 128 || c4 < BN / 4);
                if (ok) {
                    float4 v = *(const float4*)(B + (size_t)gk * ldb + n0 + c4 * 4);
                    pb[i][0] = v.x; pb[i][1] = v.y; pb[i][2] = v.z; pb[i][3] = v.w;
                } else {
                    pb[i][0] = pb[i][1] = pb[i][2] = pb[i][3] = 0.f;
                }
            }
        }

#pragma unroll
        for (int ks = 0; ks < BK; ks += 8) {
            uint32_t af[4][4];
            const int kk_ = ks + (lane & 3);
            const int gmr = lane >> 2;
#pragma unroll
            for (int mt = 0; mt < 4; ++mt) {
                int mm = wm + mt * 16 + gmr;
                af[mt][0] = __float_as_uint(As[mm][kk_]);
                af[mt][1] = __float_as_uint(As[mm + 8][kk_]);
                af[mt][2] = __float_as_uint(As[mm][kk_ + 4]);
                af[mt][3] = __float_as_uint(As[mm + 8][kk_ + 4]);
            }
#pragma unroll
            for (int nt = 0; nt < NT; ++nt) {
                uint32_t bf[2];
                int nn = wn + nt * 8 + gmr;
                bf[0] = __float_as_uint(Bs[kk_][nn]);
                bf[1] = __float_as_uint(Bs[kk_ + 4][nn]);
#pragma unroll
                for (int mt = 0; mt < 4; ++mt)
                    mma8(acc[mt][nt], af[mt], bf);
            }
        }
        __syncthreads();
        if (!more) break;
        k0 = knext;
    }

    // ---- epilogue ----
#pragma unroll
    for (int mt = 0; mt < 4; ++mt) {
#pragma unroll
        for (int nt = 0; nt < NT; ++nt) {
#pragma unroll
            for (int e = 0; e < 4; ++e) {
                int m = m0 + wm + mt * 16 + (lane >> 2) + ((e >= 2) ? 8 : 0);
                int n = n0 + wn + nt * 8 + (lane & 3) * 2 + (e & 1);
                if (m >= M || n >= N) continue;
                float v = acc[mt][nt][e];
                size_t idx;
                if (EPI == E_PATCH) {
                    int bb = m >> 10, np = m & 1023;
                    idx = ((size_t)bb * SEQ + 1 + np) * DMODEL + n;
                    v += bias[n] + aux[(size_t)(1 + np) * DMODEL + n];
                } else {
                    idx = (size_t)m * ldc + n;
                    if (EPI == E_RELU) { v += bias[n]; v = fmaxf(v, 0.f); }
                    else if (EPI == E_RES) { v += bias[n] + C[idx]; }
                }
                C[idx] = v;
            }
        }
    }
}

// ---------------- flash attention (distance softmax), tf32 mma ----------------
// grid (9 qtiles, 64 bh), 256 threads = 8 warps. Each warp: 16 q-rows.
// K/V tiles of 64 tokens, double-buffered smem. S never materialized.
#define KTILES 17
#define KSL 100   // Ks row stride (floats): banks 4j+a -> conflict-free
#define VSL 104   // Vs row stride: banks 8a+b -> conflict-free
#define KS_ST (64 * KSL)
#define VS_ST (64 * VSL)
#define FLASH_SMEM ((2 * KS_ST + 2 * VS_ST + 2 * 64) * 4)

__global__ __launch_bounds__(256, 1)
void flash_kernel(const float* __restrict__ Qg, const float* __restrict__ Kg,
                  const float* __restrict__ Vg, const float* __restrict__ qqg,
                  const float* __restrict__ kkg, float* __restrict__ Og)
{
    extern __shared__ float sm[];
    float* Ks  = sm;
    float* Vs  = sm + 2 * KS_ST;
    float* kks = Vs + 2 * VS_ST;

    const int z = blockIdx.y, b = z >> 2, hh = z & 3;
    const int q0 = blockIdx.x * 128;
    const int tid = threadIdx.x, lane = tid & 31, w = tid >> 5;
    const int rr = q0 + w * 16 + (lane >> 2);

    const float* qqz = qqg + (size_t)z * SEQ;
    const float* kkz = kkg + (size_t)z * SEQ;

    // Q fragments in registers (clamped rows; invalid rows masked at store)
    const int r0c = min(rr, SEQ - 1), r1c = min(rr + 8, SEQ - 1);
    const float* q0p = Qg + ((size_t)b * SEQ + r0c) * DMODEL + hh * HDIM;
    const float* q1p = Qg + ((size_t)b * SEQ + r1c) * DMODEL + hh * HDIM;
    uint32_t qf[12][4];
#pragma unroll
    for (int s = 0; s < 12; ++s) {
        int c0 = s * 8 + (lane & 3);
        qf[s][0] = tf32u(q0p[c0]);
        qf[s][1] = tf32u(q1p[c0]);
        qf[s][2] = tf32u(q0p[c0 + 4]);
        qf[s][3] = tf32u(q1p[c0 + 4]);
    }
    const float qq0 = qqz[r0c], qq1 = qqz[r1c];

    float o[12][4];
#pragma unroll
    for (int n = 0; n < 12; ++n)
#pragma unroll
        for (int e = 0; e < 4; ++e) o[n][e] = 0.f;
    float m0 = -1e30f, m1 = -1e30f, l0 = 0.f, l1 = 0.f;

    const int ltok = tid / 4;            // loader: not used (see f4 scheme below)
    (void)ltok;

    // ---- preload tile 0 ----
    {
        float4 kr[6], vr[6];
#pragma unroll
        for (int j = 0; j < 6; ++j) {
            int i = tid + j * 256;
            int t = i / 24, d4 = i % 24;
            int tg = t;  // kt=0
            if (tg < SEQ) {
                kr[j] = *(const float4*)(Kg + ((size_t)b * SEQ + tg) * DMODEL + hh * HDIM + d4 * 4);
                vr[j] = *(const float4*)(Vg + ((size_t)b * SEQ + tg) * DMODEL + hh * HDIM + d4 * 4);
            } else {
                kr[j] = make_float4(0.f, 0.f, 0.f, 0.f);
                vr[j] = kr[j];
            }
        }
#pragma unroll
        for (int j = 0; j < 6; ++j) {
            int i = tid + j * 256;
            int t = i / 24, d4 = i % 24;
            float* kd = &Ks[t * KSL + d4 * 4];
            kd[0] = cvt_tf32(kr[j].x); kd[1] = cvt_tf32(kr[j].y);
            kd[2] = cvt_tf32(kr[j].z); kd[3] = cvt_tf32(kr[j].w);
            float* vd = &Vs[t * VSL + d4 * 4];
            vd[0] = cvt_tf32(vr[j].x); vd[1] = cvt_tf32(vr[j].y);
            vd[2] = cvt_tf32(vr[j].z); vd[3] = cvt_tf32(vr[j].w);
        }
        if (tid < 64) kks[tid] = kkz[min(tid, SEQ - 1)];
        __syncthreads();
    }

    const int srcA = (lane & ~3) | ((lane & 3) >> 1);
    const int srcB = srcA + 2;
    const bool odd = (lane & 1);

    for (int kt = 0; kt < KTILES; ++kt) {
        const int st = kt & 1;
        const bool more = (kt + 1 < KTILES);
        float4 kr[6];

        // prefetch next K
        if (more) {
#pragma unroll
            for (int j = 0; j < 6; ++j) {
                int i = tid + j * 256;
                int t = i / 24, d4 = i % 24;
                int tg = (kt + 1) * 64 + t;
                kr[j] = (tg < SEQ)
                    ? *(const float4*)(Kg + ((size_t)b * SEQ + tg) * DMODEL + hh * HDIM + d4 * 4)
                    : make_float4(0.f, 0.f, 0.f, 0.f);
            }
        }

        // ---- scores: S = Q @ K^T (tile) ----
        float sc[8][4];
#pragma unroll
        for (int nt = 0; nt < 8; ++nt)
#pragma unroll
            for (int e = 0; e < 4; ++e) sc[nt][e] = 0.f;

        const float* Kst = Ks + st * KS_ST;
#pragma unroll
        for (int s = 0; s < 12; ++s) {
#pragma unroll
            for (int nt = 0; nt < 8; ++nt) {
                int nn = nt * 8 + (lane >> 2);
                uint32_t bf[2];
                bf[0] = __float_as_uint(Kst[nn * KSL + s * 8 + (lane & 3)]);
                bf[1] = __float_as_uint(Kst[nn * KSL + s * 8 + 4 + (lane & 3)]);
                mma8(sc[nt], qf[s], bf);
            }
        }

        // store next K tile
        if (more) {
            float* Kdst = Ks + (st ^ 1) * KS_ST;
#pragma unroll
            for (int j = 0; j < 6; ++j) {
                int i = tid + j * 256;
                int t = i / 24, d4 = i % 24;
                float* kd = &Kdst[t * KSL + d4 * 4];
                kd[0] = cvt_tf32(kr[j].x); kd[1] = cvt_tf32(kr[j].y);
                kd[2] = cvt_tf32(kr[j].z); kd[3] = cvt_tf32(kr[j].w);
            }
        }

        // prefetch next V
        float4 vr[6];
        if (more) {
#pragma unroll
            for (int j = 0; j < 6; ++j) {
                int i = tid + j * 256;
                int t = i / 24, d4 = i % 24;
                int tg = (kt + 1) * 64 + t;
                vr[j] = (tg < SEQ)
                    ? *(const float4*)(Vg + ((size_t)b * SEQ + tg) * DMODEL + hh * HDIM + d4 * 4)
                    : make_float4(0.f, 0.f, 0.f, 0.f);
            }
        }

        // ---- distance + online softmax ----
        const float* kkst = kks + st * 64;
        float mt0 = -1e30f, mt1 = -1e30f;
#pragma unroll
        for (int nt = 0; nt < 8; ++nt) {
#pragma unroll
            for (int e = 0; e < 4; ++e) {
                int colL = nt * 8 + 2 * (lane & 3) + (e & 1);
                int colG = kt * 64 + colL;
                float qv = (e < 2) ? qq0 : qq1;
                float d2 = qv + kkst[colL] - 2.f * sc[nt][e];
                float sv = sqrtf(fmaxf(d2, 0.f)) * SCALE_ATT;
                sv = (colG < SEQ) ? sv : -1e30f;
                sc[nt][e] = sv;
                if (e < 2) mt0 = fmaxf(mt0, sv);
                else       mt1 = fmaxf(mt1, sv);
            }
        }
        mt0 = fmaxf(mt0, __shfl_xor_sync(0xffffffffu, mt0, 1));
        mt0 = fmaxf(mt0, __shfl_xor_sync(0xffffffffu, mt0, 2));
        mt1 = fmaxf(mt1, __shfl_xor_sync(0xffffffffu, mt1, 1));
        mt1 = fmaxf(mt1, __shfl_xor_sync(0xffffffffu, mt1, 2));
        float mn0 = fmaxf(m0, mt0), mn1 = fmaxf(m1, mt1);
        float a0 = __expf(m0 - mn0), a1 = __expf(m1 - mn1);
        m0 = mn0; m1 = mn1;

        float s0 = 0.f, s1 = 0.f;
#pragma unroll
        for (int nt = 0; nt < 8; ++nt) {
#pragma unroll
            for (int e = 0; e < 4; ++e) {
                float p = __expf(sc[nt][e] - ((e < 2) ? m0 : m1));
                if (e < 2) s0 += p; else s1 += p;
                sc[nt][e] = p;
            }
        }
        s0 += __shfl_xor_sync(0xffffffffu, s0, 1);
        s0 += __shfl_xor_sync(0xffffffffu, s0, 2);
        s1 += __shfl_xor_sync(0xffffffffu, s1, 1);
        s1 += __shfl_xor_sync(0xffffffffu, s1, 2);
        l0 = l0 * a0 + s0;
        l1 = l1 * a1 + s1;
#pragma unroll
        for (int n = 0; n < 12; ++n) {
            o[n][0] *= a0; o[n][1] *= a0;
            o[n][2] *= a1; o[n][3] *= a1;
        }

        // ---- PV: O += P @ V ----
        const float* Vst = Vs + st * VS_ST;
#pragma unroll
        for (int s = 0; s < 8; ++s) {
            float x0 = __shfl_sync(0xffffffffu, sc[s][0], srcA);
            float x1 = __shfl_sync(0xffffffffu, sc[s][1], srcA);
            float x2 = __shfl_sync(0xffffffffu, sc[s][2], srcA);
            float x3 = __shfl_sync(0xffffffffu, sc[s][3], srcA);
            float y0 = __shfl_sync(0xffffffffu, sc[s][0], srcB);
            float y1 = __shfl_sync(0xffffffffu, sc[s][1], srcB);
            float y2 = __shfl_sync(0xffffffffu, sc[s][2], srcB);
            float y3 = __shfl_sync(0xffffffffu, sc[s][3], srcB);
            uint32_t af[4];
            af[0] = tf32u(odd ? x1 : x0);
            af[1] = tf32u(odd ? x3 : x2);
            af[2] = tf32u(odd ? y1 : y0);
            af[3] = tf32u(odd ? y3 : y2);
#pragma unroll
            for (int nt = 0; nt < 12; ++nt) {
                int nn = nt * 8 + (lane >> 2);
                uint32_t bf[2];
                bf[0] = __float_as_uint(Vst[(s * 8 + (lane & 3)) * VSL + nn]);
                bf[1] = __float_as_uint(Vst[(s * 8 + 4 + (lane & 3)) * VSL + nn]);
                mma8(o[nt], af, bf);
            }
        }

        // store next V + kk
        if (more) {
            float* Vdst = Vs + (st ^ 1) * VS_ST;
#pragma unroll
            for (int j = 0; j < 6; ++j) {
                int i = tid + j * 256;
                int t = i / 24, d4 = i % 24;
                float* vd = &Vdst[t * VSL + d4 * 4];
                vd[0] = cvt_tf32(vr[j].x); vd[1] = cvt_tf32(vr[j].y);
                vd[2] = cvt_tf32(vr[j].z); vd[3] = cvt_tf32(vr[j].w);
            }
            if (tid < 64) kks[(st ^ 1) * 64 + tid] = kkz[min((kt + 1) * 64 + tid, SEQ - 1)];
        }
        __syncthreads();
    }

    // ---- write out ----
    float inv0 = 1.f / l0, inv1 = 1.f / l1;
    if (rr < SEQ) {
        float* orow = Og + ((size_t)b * SEQ + rr) * DMODEL + hh * HDIM;
#pragma unroll
        for (int nt = 0; nt < 12; ++nt) {
            int col = nt * 8 + 2 * (lane & 3);
            float2 vv = make_float2(o[nt][0] * inv0, o[nt][1] * inv0);
            *(float2*)(orow + col) = vv;
        }
    }
    if (rr + 8 < SEQ) {
        float* orow = Og + ((size_t)b * SEQ + rr + 8) * DMODEL + hh * HDIM;
#pragma unroll
        for (int nt = 0; nt < 12; ++nt) {
            int col = nt * 8 + 2 * (lane & 3);
            float2 vv = make_float2(o[nt][2] * inv1, o[nt][3] * inv1);
            *(float2*)(orow + col) = vv;
        }
    }
}

// ---------------- conv weight transpose ----------------
__global__ void transpose_w_kernel(const float* __restrict__ cw, float* __restrict__ wt)
{
    __shared__ float t[32][33];
    int k0 = blockIdx.x * 32, n0 = blockIdx.y * 32;
    int tx = threadIdx.x, ty = threadIdx.y;
    for (int i = ty; i < 32; i += 8)
        t[i][tx] = cw[(size_t)(n0 + i) * (CIN * PATCH * PATCH) + k0 + tx];
    __syncthreads();
    for (int i = ty; i < 32; i += 8)
        wt[(size_t)(k0 + i) * DMODEL + n0 + tx] = t[tx][i];
}

// ---------------- per-row |q|^2 and |k|^2 per head ----------------
__global__ void sumsq_kernel(const float* __restrict__ q, const float* __restrict__ k,
                             float* __restrict__ qq, float* __restrict__ kk)
{
    int gw = (blockIdx.x * blockDim.x + threadIdx.x) >> 5;
    int lane = threadIdx.x & 31;
    if (gw >= BH * SEQ) return;
    int z = gw / SEQ, t = gw % SEQ;
    int b = z >> 2, h = z & 3;
    const float* qr = q + ((size_t)b * SEQ + t) * DMODEL + h * HDIM;
    const float* kr = k + ((size_t)b * SEQ + t) * DMODEL + h * HDIM;
    float sq = 0.f, sk = 0.f;
#pragma unroll
    for (int i = 0; i < 3; ++i) {
        float a = qr[lane + 32 * i]; sq += a * a;
        float c = kr[lane + 32 * i]; sk += c * c;
    }
#pragma unroll
    for (int o = 16; o > 0; o >>= 1) {
        sq += __shfl_down_sync(0xffffffffu, sq, o);
        sk += __shfl_down_sync(0xffffffffu, sk, o);
    }
    if (lane == 0) { qq[gw] = sq; kk[gw] = sk; }
}

// ---------------- cls row ----------------
__global__ void cls_kernel(const float* __restrict__ cls_token,
                           const float* __restrict__ pos, float* __restrict__ h)
{
    int b = blockIdx.x, d = threadIdx.x;
    h[(size_t)b * SEQ * DMODEL + d] = cls_token[d] + pos[d];
}

// ---------------- LayerNorm, warp per row ----------------
__global__ void ln_kernel(const float* __restrict__ x, float* __restrict__ y,
                          const float* __restrict__ s, const float* __restrict__ bb)
{
    int w = threadIdx.x >> 5, lane = threadIdx.x & 31;
    int row = blockIdx.x * 8 + w;
    const float4* xr = (const float4*)(x + (size_t)row * DMODEL);
    float4* yr = (float4*)(y + (size_t)row * DMODEL);

    float4 a = xr[lane], c = xr[lane + 32], d = xr[lane + 64];
    float sum = a.x + a.y + a.z + a.w + c.x + c.y + c.z + c.w + d.x + d.y + d.z + d.w;
#pragma unroll
    for (int o = 16; o > 0; o >>= 1) sum += __shfl_xor_sync(0xffffffffu, sum, o);
    float mean = sum * (1.f / DMODEL);

    a.x -= mean; a.y -= mean; a.z -= mean; a.w -= mean;
    c.x -= mean; c.y -= mean; c.z -= mean; c.w -= mean;
    d.x -= mean; d.y -= mean; d.z -= mean; d.w -= mean;
    float sq = a.x*a.x + a.y*a.y + a.z*a.z + a.w*a.w
             + c.x*c.x + c.y*c.y + c.z*c.z + c.w*c.w
             + d.x*d.x + d.y*d.y + d.z*d.z + d.w*d.w;
#pragma unroll
    for (int o = 16; o > 0; o >>= 1) sq += __shfl_xor_sync(0xffffffffu, sq, o);
    float inv = rsqrtf(sq * (1.f / DMODEL) + 1e-5f);

    const float4* sp = (const float4*)s;
    const float4* bp = (const float4*)bb;
    float4 s0 = sp[lane], s1 = sp[lane + 32], s2 = sp[lane + 64];
    float4 b0 = bp[lane], b1 = bp[lane + 32], b2 = bp[lane + 64];
    float4 r;
    r.x = a.x*inv*s0.x + b0.x; r.y = a.y*inv*s0.y + b0.y;
    r.z = a.z*inv*s0.z + b0.z; r.w = a.w*inv*s0.w + b0.w;
    yr[lane] = r;
    r.x = c.x*inv*s1.x + b1.x; r.y = c.y*inv*s1.y + b1.y;
    r.z = c.z*inv*s1.z + b1.z; r.w = c.w*inv*s1.w + b1.w;
    yr[lane + 32] = r;
    r.x = d.x*inv*s2.x + b2.x; r.y = d.y*inv*s2.y + b2.y;
    r.z = d.z*inv*s2.z + b2.z; r.w = d.w*inv*s2.w + b2.w;
    yr[lane + 64] = r;
}

// ---------------- final LN(cls) + proj + loss ----------------
__global__ void final_kernel(const float* __restrict__ h,
                             const float* __restrict__ lnf_s, const float* __restrict__ lnf_b,
                             const float* __restrict__ pw, const float* __restrict__ pb,
                             const int* __restrict__ targets,
                             float* __restrict__ out, int out_size)
{
    int tid = threadIdx.x;
    __shared__ float losses[BATCH];
    if (tid < BATCH) {
        const float* xr = h + (size_t)tid * SEQ * DMODEL;
        float sum = 0.f;
        for (int d = 0; d < DMODEL; ++d) sum += xr[d];
        float mean = sum * (1.f / DMODEL);
        float sq = 0.f;
        for (int d = 0; d < DMODEL; ++d) {
            float dv = xr[d] - mean;
            sq += dv * dv;
        }
        float inv = rsqrtf(sq * (1.f / DMODEL) + 1e-5f);
        float l0 = pb[0], l1 = pb[1];
        for (int d = 0; d < DMODEL; ++d) {
            float nd = (xr[d] - mean) * inv * lnf_s[d] + lnf_b[d];
            l0 += nd * pw[d * NCLS + 0];
            l1 += nd * pw[d * NCLS + 1];
        }
        out[tid * 2 + 0] = l0;
        out[tid * 2 + 1] = l1;
        float mxl = fmaxf(l0, l1);
        float lse = mxl + logf(expf(l0 - mxl) + expf(l1 - mxl));
        int t = targets[tid];
        losses[tid] = lse - (t == 0 ? l0 : l1);
    }
    __syncthreads();
    if (tid == 0) {
        float s = 0.f;
        for (int i = 0; i < BATCH; ++i) s += losses[i];
        if (out_size > BATCH * NCLS) out[BATCH * NCLS] = s * (1.f / BATCH);
    }
}

// ---------------- launch ----------------
extern "C" void kernel_launch(void* const* d_in, const int* in_sizes, int n_in,
                              void* d_out, int out_size)
{
    const float* x       = (const float*)d_in[0];
    const int*   targets = (const int*)  d_in[1];
    const float* conv_w  = (const float*)d_in[2];
    const float* conv_b  = (const float*)d_in[3];
    const float* cls_tok = (const float*)d_in[4];
    const float* pos_emb = (const float*)d_in[5];
    const float* ln1_s   = (const float*)d_in[6];
    const float* ln1_b   = (const float*)d_in[7];
    const float* ln2_s   = (const float*)d_in[8];
    const float* ln2_b   = (const float*)d_in[9];
    const float* wq      = (const float*)d_in[10];
    const float* wk      = (const float*)d_in[11];
    const float* wv      = (const float*)d_in[12];
    const float* wo      = (const float*)d_in[13];
    const float* bo      = (const float*)d_in[14];
    const float* w1      = (const float*)d_in[15];
    const float* b1      = (const float*)d_in[16];
    const float* w2      = (const float*)d_in[17];
    const float* b2      = (const float*)d_in[18];
    const float* lnf_s   = (const float*)d_in[19];
    const float* lnf_b   = (const float*)d_in[20];
    const float* proj_w  = (const float*)d_in[21];
    const float* proj_b  = (const float*)d_in[22];

    float *h, *hn, *q, *k, *v, *vals, *f, *qq, *kk, *wt;
    cudaGetSymbolAddress((void**)&h,    g_h);
    cudaGetSymbolAddress((void**)&hn,   g_hn);
    cudaGetSymbolAddress((void**)&q,    g_q);
    cudaGetSymbolAddress((void**)&k,    g_k);
    cudaGetSymbolAddress((void**)&v,    g_v);
    cudaGetSymbolAddress((void**)&vals, g_vals);
    cudaGetSymbolAddress((void**)&f,    g_f);
    cudaGetSymbolAddress((void**)&qq,   g_qq);
    cudaGetSymbolAddress((void**)&kk,   g_kk);
    cudaGetSymbolAddress((void**)&wt,   g_wt);

    static bool attr_set = false;
    if (!attr_set) {
        cudaFuncSetAttribute(flash_kernel,
                             cudaFuncAttributeMaxDynamicSharedMemorySize, FLASH_SMEM);
        attr_set = true;
    }

    transpose_w_kernel<<<dim3(24, 12), dim3(32, 8)>>>(conv_w, wt);
    gemm_tf32<E_PATCH, 128, 3><<<dim3(3, 128, 1), 256>>>(
        x, 0, wt, DMODEL, h, DMODEL, conv_b, pos_emb,
        nullptr, nullptr, nullptr, nullptr,
        BATCH * NPATCH, DMODEL, CIN * PATCH * PATCH);
    cls_kernel<<<BATCH, DMODEL>>>(cls_tok, pos_emb, h);

    const int MT = (MROWS + 127) / 128;  // 129
    for (int i = 0; i < NBLOCKS; ++i) {
        const float* wqi = wq + (size_t)i * DMODEL * DMODEL;
        const float* wki = wk + (size_t)i * DMODEL * DMODEL;
        const float* wvi = wv + (size_t)i * DMODEL * DMODEL;
        const float* woi = wo + (size_t)i * DMODEL * DMODEL;
        const float* w1i = w1 + (size_t)i * DMODEL * FFDIM;
        const float* w2i = w2 + (size_t)i * FFDIM * DMODEL;

        ln_kernel<<<MROWS / 8, 256>>>(h, hn, ln1_s + i * DMODEL, ln1_b + i * DMODEL);

        // fused QKV: grid.x 0-2 -> Q, 3-5 -> K, 6-8 -> V
        gemm_tf32<E_NONE, 128, 4><<<dim3(9, MT, 1), 256>>>(
            hn, DMODEL, wqi, DMODEL, q, DMODEL, nullptr, nullptr,
            wki, wvi, k, v, MROWS, DMODEL, DMODEL);

        sumsq_kernel<<<(BH * SEQ + 7) / 8, 256>>>(q, k, qq, kk);

        flash_kernel<<<dim3(9, BH), 256, FLASH_SMEM>>>(q, k, v, qq, kk, vals);

        gemm_tf32<E_RES, 128, 0><<<dim3(3, MT, 1), 256>>>(
            vals, DMODEL, woi, DMODEL, h, DMODEL, bo + i * DMODEL, nullptr,
            nullptr, nullptr, nullptr, nullptr, MROWS, DMODEL, DMODEL);

        ln_kernel<<<MROWS / 8, 256>>>(h, hn, ln2_s + i * DMODEL, ln2_b + i * DMODEL);

        gemm_tf32<E_RELU, 128, 0><<<dim3(12, MT, 1), 256>>>(
            hn, DMODEL, w1i, FFDIM, f, FFDIM, b1 + i * FFDIM, nullptr,
            nullptr, nullptr, nullptr, nullptr, MROWS, FFDIM, DMODEL);

        gemm_tf32<E_RES, 128, 0><<<dim3(3, MT, 1), 256>>>(
            f, FFDIM, w2i, DMODEL, h, DMODEL, b2 + i * DMODEL, nullptr,
            nullptr, nullptr, nullptr, nullptr, MROWS, DMODEL, FFDIM);
    }

    final_kernel<<<1, 32>>>(h, lnf_s, lnf_b, proj_w, proj_b, targets,
                            (float*)d_out, out_size);
}